// round 15
// baseline (speedup 1.0000x reference)
#include <cuda_runtime.h>
#include <cuda_fp16.h>

// WarpImageLayer: bilinear warp with flow, border value 0. Fused single kernel.
// Per block: 64x32 output tile + 24px margin = 112x80 footprint staged in smem
// as ONE 8B entry per pixel: {half2(c0,c1), half2(c2,pad)} -> 71680B smem,
// 3 CTAs/SM x 512 thr = 1536 thr/SM. Gathers: 4x LDS.64 per pixel (halved
// instruction count vs split planes at equal crossbar bytes).
// Each thread owns 4 consecutive x-pixels: flow read = 2x LDG.128 / 4px,
// output = 3x STG.128 / 4px (4x fewer L1 ops at equal bytes).
// Footprint loaded with clamped indices so smem[local]==img[clamp(global)].
// ~2-3% out-of-footprint samples -> predicated fp32 global fallback.

#define N_  32
#define C_  3
#define H_  384
#define W_  512
#define HW_ (H_ * W_)

#define TX     64
#define TY     32
#define MARGIN 24
#define FX     (TX + 2 * MARGIN)     // 112
#define FY     (TY + 2 * MARGIN)     // 80
#define FF     (FX * FY)             // 8960
#define SMEM_BYTES (FF * 8)          // 71680
#define NT     512

__device__ __forceinline__ unsigned int pack_h2(float a, float b) {
    __half2 h = __floats2half2_rn(a, b);
    return *reinterpret_cast<unsigned int*>(&h);
}
__device__ __forceinline__ float2 h2f(unsigned int u) {
    __half2 h = *reinterpret_cast<__half2*>(&u);
    return __half22float2(h);
}

__global__ __launch_bounds__(NT, 3) void warp_fused(
    const float* __restrict__ img,
    const float* __restrict__ flow,
    float* __restrict__ out)
{
    extern __shared__ uint2 entries[];   // FF x 8B: {h2(c0,c1), h2(c2,0)}

    const int tx0 = blockIdx.x * TX;
    const int ty0 = blockIdx.y * TY;
    const int n   = blockIdx.z;
    const int fx0 = tx0 - MARGIN;        // mod 4 == 0
    const int fy0 = ty0 - MARGIN;

    const float* ib = img + (size_t)n * C_ * HW_;
    const int tid = threadIdx.x;

    // ---- load phase: footprint -> smem (quad = 4 consecutive px) ----
    #pragma unroll
    for (int q = tid; q < FF / 4; q += NT) {
        int e  = q * 4;
        int fr = e / FX;
        int fc = e - fr * FX;            // multiple of 4
        int gv = min(max(fy0 + fr, 0), H_ - 1);
        int gu0 = fx0 + fc;              // 4-aligned when in range

        float4 c0, c1, c2;
        if (gu0 >= 0 && gu0 + 3 <= W_ - 1) {
            int off = gv * W_ + gu0;
            c0 = __ldg((const float4*)(ib + off));
            c1 = __ldg((const float4*)(ib + HW_ + off));
            c2 = __ldg((const float4*)(ib + 2 * HW_ + off));
        } else {
            float b0[4], b1[4], b2[4];
            #pragma unroll
            for (int k = 0; k < 4; k++) {
                int gu = min(max(gu0 + k, 0), W_ - 1);
                int off = gv * W_ + gu;
                b0[k] = __ldg(ib + off);
                b1[k] = __ldg(ib + HW_ + off);
                b2[k] = __ldg(ib + 2 * HW_ + off);
            }
            c0 = make_float4(b0[0], b0[1], b0[2], b0[3]);
            c1 = make_float4(b1[0], b1[1], b1[2], b1[3]);
            c2 = make_float4(b2[0], b2[1], b2[2], b2[3]);
        }

        uint4 lo, hi;
        lo.x = pack_h2(c0.x, c1.x);  lo.y = pack_h2(c2.x, 0.f);
        lo.z = pack_h2(c0.y, c1.y);  lo.w = pack_h2(c2.y, 0.f);
        hi.x = pack_h2(c0.z, c1.z);  hi.y = pack_h2(c2.z, 0.f);
        hi.z = pack_h2(c0.w, c1.w);  hi.w = pack_h2(c2.w, 0.f);
        *(uint4*)(entries + e)     = lo;              // STS.128
        *(uint4*)(entries + e + 2) = hi;              // STS.128
    }
    __syncthreads();

    // ---- gather phase: 4 consecutive x-pixels per thread ----
    const int xq  = tid & 15;            // 0..15  (16 quads cover TX=64)
    const int ly  = tid >> 4;            // 0..31
    const int gx0 = tx0 + xq * 4;
    const int gy  = ty0 + ly;
    const int fo  = gy * W_ + gx0;

    const float* flbase = flow + (size_t)n * 2 * HW_;
    float* obase = out + (size_t)n * C_ * HW_;

    float4 fu4 = __ldg((const float4*)(flbase + fo));          // u-flow x4
    float4 fv4 = __ldg((const float4*)(flbase + HW_ + fo));    // v-flow x4
    const float* fu = (const float*)&fu4;
    const float* fv = (const float*)&fv4;

    float r0[4], r1[4], r2[4];

    #pragma unroll
    for (int k = 0; k < 4; k++) {
        int gx = gx0 + k;
        float u = (float)gx + fu[k] * (float)W_;
        float v = (float)gy + fv[k] * (float)H_;

        float u0f = floorf(u);
        float v0f = floorf(v);
        float du = u - u0f;
        float dv = v - v0f;

        bool valid = (u >= 0.0f) && (u <= (float)(W_ - 1)) &&
                     (v >= 0.0f) && (v <= (float)(H_ - 1));

        float s0 = 0.f, s1 = 0.f, s2 = 0.f;
        if (valid) {
            int u0 = (int)u0f;           // in [0, W-1]
            int v0 = (int)v0f;           // in [0, H-1]
            float w00 = (1.f - du) * (1.f - dv);
            float w10 = du * (1.f - dv);
            float w01 = (1.f - du) * dv;
            float w11 = du * dv;

            int lu = u0 - fx0;
            int lv = v0 - fy0;
            if (lu >= 0 && lu < FX - 1 && lv >= 0 && lv < FY - 1) {
                int i00 = lv * FX + lu;
                int i01 = i00 + FX;

                uint2 e00 = entries[i00];       // LDS.64
                uint2 e10 = entries[i00 + 1];
                uint2 e01 = entries[i01];
                uint2 e11 = entries[i01 + 1];

                float2 a = h2f(e00.x); float2 az = h2f(e00.y);
                float2 b = h2f(e10.x); float2 bz = h2f(e10.y);
                float2 c = h2f(e01.x); float2 cz = h2f(e01.y);
                float2 d = h2f(e11.x); float2 dz = h2f(e11.y);

                s0 = fmaf(w00, a.x,  fmaf(w10, b.x,  fmaf(w01, c.x,  w11 * d.x)));
                s1 = fmaf(w00, a.y,  fmaf(w10, b.y,  fmaf(w01, c.y,  w11 * d.y)));
                s2 = fmaf(w00, az.x, fmaf(w10, bz.x, fmaf(w01, cz.x, w11 * dz.x)));
            } else {
                // rare fallback (~2-3%): fp32 global gather with clamp
                int u0c = min(max(u0, 0), W_ - 1);
                int u1c = min(u0 + 1, W_ - 1);
                int v0c = min(max(v0, 0), H_ - 1);
                int v1c = min(v0 + 1, H_ - 1);
                int o00 = v0c * W_ + u0c, o10 = v0c * W_ + u1c;
                int o01 = v1c * W_ + u0c, o11 = v1c * W_ + u1c;
                #pragma unroll
                for (int cc = 0; cc < C_; cc++) {
                    const float* p = ib + cc * HW_;
                    float g = fmaf(w00, __ldg(p + o00),
                              fmaf(w10, __ldg(p + o10),
                              fmaf(w01, __ldg(p + o01),
                                   w11 * __ldg(p + o11))));
                    if (cc == 0) s0 = g; else if (cc == 1) s1 = g; else s2 = g;
                }
            }
        }
        r0[k] = s0; r1[k] = s1; r2[k] = s2;
    }

    *(float4*)(obase + fo)            = make_float4(r0[0], r0[1], r0[2], r0[3]);
    *(float4*)(obase + HW_ + fo)      = make_float4(r1[0], r1[1], r1[2], r1[3]);
    *(float4*)(obase + 2 * HW_ + fo)  = make_float4(r2[0], r2[1], r2[2], r2[3]);
}

extern "C" void kernel_launch(void* const* d_in, const int* in_sizes, int n_in,
                              void* d_out, int out_size)
{
    const float* img  = (const float*)d_in[0];
    const float* flow = (const float*)d_in[1];
    float*       out  = (float*)d_out;

    cudaFuncSetAttribute(warp_fused,
                         cudaFuncAttributeMaxDynamicSharedMemorySize,
                         SMEM_BYTES);

    dim3 grid(W_ / TX, H_ / TY, N_);   // (8, 12, 32)
    warp_fused<<<grid, NT, SMEM_BYTES>>>(img, flow, out);
}

// round 17
// speedup vs baseline: 1.5264x; 1.5264x over previous
#include <cuda_runtime.h>
#include <cuda_fp16.h>

// WarpImageLayer: bilinear warp with flow, border value 0. Fused single kernel.
// 64x32 output tile + 24px margin = 112x80 footprint in smem, ONE 8B entry
// per pixel {half2(c0,c1), half2(c2,pad)} with PADDED row stride 114 entries
// (912B = 32 mod 128 -> bank = 2*lu + 4*lv mod 32: row coordinate decorrelates
// banks; round 15's stride 112*8 was 0 mod 128 which serialized the crossbar).
// Gather = 4x LDS.64 per pixel (half the LDS issue slots of split planes).
// Lane mapping: 32 consecutive x per warp (max bank spread, coalesced I/O).
// smem 72960B -> 3 CTAs x 512 thr = 1536 thr/SM.
// Footprint loaded with clamped indices so smem[local]==img[clamp(global)].
// ~2-3% out-of-footprint samples -> predicated fp32 global fallback.

#define N_  32
#define C_  3
#define H_  384
#define W_  512
#define HW_ (H_ * W_)

#define TX     64
#define TY     32
#define MARGIN 24
#define FX     (TX + 2 * MARGIN)     // 112 (data columns)
#define FXP    114                   // padded stride (even: keeps 16B align)
#define FY     (TY + 2 * MARGIN)     // 80
#define SMEM_BYTES (FXP * FY * 8)    // 72960
#define NT     512

__device__ __forceinline__ unsigned int pack_h2(float a, float b) {
    __half2 h = __floats2half2_rn(a, b);
    return *reinterpret_cast<unsigned int*>(&h);
}
__device__ __forceinline__ float2 h2f(unsigned int u) {
    __half2 h = *reinterpret_cast<__half2*>(&u);
    return __half22float2(h);
}

__global__ __launch_bounds__(NT, 3) void warp_fused(
    const float* __restrict__ img,
    const float* __restrict__ flow,
    float* __restrict__ out)
{
    extern __shared__ uint2 entries[];   // FXP*FY, 8B each

    const int tx0 = blockIdx.x * TX;
    const int ty0 = blockIdx.y * TY;
    const int n   = blockIdx.z;
    const int fx0 = tx0 - MARGIN;        // mod 4 == 0
    const int fy0 = ty0 - MARGIN;

    const float* ib = img + (size_t)n * C_ * HW_;
    const int tid = threadIdx.x;

    // ---- load phase: footprint -> smem (quad = 4 consecutive px) ----
    #pragma unroll
    for (int q = tid; q < (FX * FY) / 4; q += NT) {
        int e  = q * 4;
        int fr = e / FX;
        int fc = e - fr * FX;            // multiple of 4
        int gv = min(max(fy0 + fr, 0), H_ - 1);
        int gu0 = fx0 + fc;              // 4-aligned when in range

        float4 c0, c1, c2;
        if (gu0 >= 0 && gu0 + 3 <= W_ - 1) {
            int off = gv * W_ + gu0;
            c0 = __ldg((const float4*)(ib + off));
            c1 = __ldg((const float4*)(ib + HW_ + off));
            c2 = __ldg((const float4*)(ib + 2 * HW_ + off));
        } else {
            float b0[4], b1[4], b2[4];
            #pragma unroll
            for (int k = 0; k < 4; k++) {
                int gu = min(max(gu0 + k, 0), W_ - 1);
                int off = gv * W_ + gu;
                b0[k] = __ldg(ib + off);
                b1[k] = __ldg(ib + HW_ + off);
                b2[k] = __ldg(ib + 2 * HW_ + off);
            }
            c0 = make_float4(b0[0], b0[1], b0[2], b0[3]);
            c1 = make_float4(b1[0], b1[1], b1[2], b1[3]);
            c2 = make_float4(b2[0], b2[1], b2[2], b2[3]);
        }

        int es = fr * FXP + fc;          // padded-stride smem index (even)
        uint4 lo, hi;
        lo.x = pack_h2(c0.x, c1.x);  lo.y = pack_h2(c2.x, 0.f);
        lo.z = pack_h2(c0.y, c1.y);  lo.w = pack_h2(c2.y, 0.f);
        hi.x = pack_h2(c0.z, c1.z);  hi.y = pack_h2(c2.z, 0.f);
        hi.z = pack_h2(c0.w, c1.w);  hi.w = pack_h2(c2.w, 0.f);
        *(uint4*)(entries + es)     = lo;             // STS.128 (16B aligned)
        *(uint4*)(entries + es + 2) = hi;             // STS.128
    }
    __syncthreads();

    // ---- gather phase: 4 output pixels per thread, consecutive-x lanes ----
    const int lx  = tid & (TX - 1);      // 0..63
    const int ly0 = tid >> 6;            // 0..7
    const int gx  = tx0 + lx;
    const float* flbase = flow + (size_t)n * 2 * HW_;
    float* obase = out + (size_t)n * C_ * HW_;

    #pragma unroll
    for (int j = 0; j < 4; j++) {
        int gy = ty0 + ly0 + 8 * j;
        int fo = gy * W_ + gx;

        float u = (float)gx + __ldg(flbase + fo) * (float)W_;
        float v = (float)gy + __ldg(flbase + HW_ + fo) * (float)H_;

        float u0f = floorf(u);
        float v0f = floorf(v);
        float du = u - u0f;
        float dv = v - v0f;

        bool valid = (u >= 0.0f) && (u <= (float)(W_ - 1)) &&
                     (v >= 0.0f) && (v <= (float)(H_ - 1));

        float r0 = 0.f, r1 = 0.f, r2 = 0.f;
        if (valid) {
            int u0 = (int)u0f;           // in [0, W-1]
            int v0 = (int)v0f;           // in [0, H-1]
            float w00 = (1.f - du) * (1.f - dv);
            float w10 = du * (1.f - dv);
            float w01 = (1.f - du) * dv;
            float w11 = du * dv;

            int lu = u0 - fx0;
            int lv = v0 - fy0;
            if (lu >= 0 && lu < FX - 1 && lv >= 0 && lv < FY - 1) {
                int i00 = lv * FXP + lu;
                int i01 = i00 + FXP;

                uint2 e00 = entries[i00];        // LDS.64
                uint2 e10 = entries[i00 + 1];    // LDS.64
                uint2 e01 = entries[i01];        // LDS.64
                uint2 e11 = entries[i01 + 1];    // LDS.64

                float2 a = h2f(e00.x); float2 az = h2f(e00.y);
                float2 b = h2f(e10.x); float2 bz = h2f(e10.y);
                float2 c = h2f(e01.x); float2 cz = h2f(e01.y);
                float2 d = h2f(e11.x); float2 dz = h2f(e11.y);

                r0 = fmaf(w00, a.x,  fmaf(w10, b.x,  fmaf(w01, c.x,  w11 * d.x)));
                r1 = fmaf(w00, a.y,  fmaf(w10, b.y,  fmaf(w01, c.y,  w11 * d.y)));
                r2 = fmaf(w00, az.x, fmaf(w10, bz.x, fmaf(w01, cz.x, w11 * dz.x)));
            } else {
                // rare fallback (~2-3%): fp32 global gather with clamp
                int u0c = min(max(u0, 0), W_ - 1);
                int u1c = min(u0 + 1, W_ - 1);
                int v0c = min(max(v0, 0), H_ - 1);
                int v1c = min(v0 + 1, H_ - 1);
                int o00 = v0c * W_ + u0c, o10 = v0c * W_ + u1c;
                int o01 = v1c * W_ + u0c, o11 = v1c * W_ + u1c;
                #pragma unroll
                for (int cc = 0; cc < C_; cc++) {
                    const float* p = ib + cc * HW_;
                    float g = fmaf(w00, __ldg(p + o00),
                              fmaf(w10, __ldg(p + o10),
                              fmaf(w01, __ldg(p + o01),
                                   w11 * __ldg(p + o11))));
                    if (cc == 0) r0 = g; else if (cc == 1) r1 = g; else r2 = g;
                }
            }
        }

        float* ob = obase + fo;
        ob[0]       = r0;
        ob[HW_]     = r1;
        ob[2 * HW_] = r2;
    }
}

extern "C" void kernel_launch(void* const* d_in, const int* in_sizes, int n_in,
                              void* d_out, int out_size)
{
    const float* img  = (const float*)d_in[0];
    const float* flow = (const float*)d_in[1];
    float*       out  = (float*)d_out;

    cudaFuncSetAttribute(warp_fused,
                         cudaFuncAttributeMaxDynamicSharedMemorySize,
                         SMEM_BYTES);

    dim3 grid(W_ / TX, H_ / TY, N_);   // (8, 12, 32)
    warp_fused<<<grid, NT, SMEM_BYTES>>>(img, flow, out);
}